// round 10
// baseline (speedup 1.0000x reference)
#include <cuda_runtime.h>
#include <cuda_bf16.h>
#include <cstdint>

#define BB 8
#define CC 64
#define NN 4096
#define KK 20
#define OO 64
#define SLOPE 0.01f
#define NEG_INF __int_as_float(0xff800000)

// ---------------- scratch ----------------
__device__ float         g_xx [BB * NN];
__device__ __nv_bfloat16 g_xhi[BB * NN * CC];   // [b][n][c], 128B rows
__device__ __nv_bfloat16 g_xlo[BB * NN * CC];
__device__ float         g_y1 [BB * NN * OO];
__device__ float         g_c  [BB * NN * OO];
__device__ int           g_idx[BB * NN * KK];

// ---------------- helpers ----------------
__device__ __forceinline__ uint32_t smem_u32(const void* p) {
    uint32_t a;
    asm("{ .reg .u64 t; cvta.to.shared.u64 t, %1; cvt.u32.u64 %0, t; }"
        : "=r"(a) : "l"(p));
    return a;
}
__device__ __forceinline__ uint32_t sw128(uint32_t off) {
    return off ^ ((off >> 3) & 0x70);
}
__device__ __forceinline__ void ldsm4(uint32_t (&r)[4], uint32_t addr) {
    asm volatile("ldmatrix.sync.aligned.m8n8.x4.shared.b16 {%0,%1,%2,%3}, [%4];"
                 : "=r"(r[0]), "=r"(r[1]), "=r"(r[2]), "=r"(r[3]) : "r"(addr));
}
__device__ __forceinline__ void mma16816(float (&d)[4], const uint32_t (&a)[4],
                                         uint32_t b0, uint32_t b1) {
    asm volatile(
        "mma.sync.aligned.m16n8k16.row.col.f32.bf16.bf16.f32 "
        "{%0,%1,%2,%3}, {%4,%5,%6,%7}, {%8,%9}, {%0,%1,%2,%3};"
        : "+f"(d[0]), "+f"(d[1]), "+f"(d[2]), "+f"(d[3])
        : "r"(a[0]), "r"(a[1]), "r"(a[2]), "r"(a[3]), "r"(b0), "r"(b1));
}

// ---------------------------------------------------------------------------
// Kernel 1: fused xx + bf16 hi/lo split, transposed to [b][n][c]
// ---------------------------------------------------------------------------
__global__ void k_pre(const float* __restrict__ x) {
    int t = blockIdx.x * 256 + threadIdx.x;      // b*NN + n
    int b = t >> 12;
    const float* xp = x + (size_t)b * CC * NN + (t & (NN - 1));
    float s = 0.f;
    uint32_t hw[CC / 2], lw[CC / 2];
#pragma unroll
    for (int c2 = 0; c2 < CC / 2; ++c2) {
        float v0 = xp[(size_t)(2 * c2) * NN];
        float v1 = xp[(size_t)(2 * c2 + 1) * NN];
        s = fmaf(v0, v0, s);
        s = fmaf(v1, v1, s);
        __nv_bfloat16 h0 = __float2bfloat16(v0);
        __nv_bfloat16 h1 = __float2bfloat16(v1);
        __nv_bfloat16 l0 = __float2bfloat16(v0 - __bfloat162float(h0));
        __nv_bfloat16 l1 = __float2bfloat16(v1 - __bfloat162float(h1));
        hw[c2] = (uint32_t)__bfloat16_as_ushort(h0) |
                 ((uint32_t)__bfloat16_as_ushort(h1) << 16);
        lw[c2] = (uint32_t)__bfloat16_as_ushort(l0) |
                 ((uint32_t)__bfloat16_as_ushort(l1) << 16);
    }
    g_xx[t] = s;
    uint4* ph = (uint4*)(g_xhi + (size_t)t * CC);
    uint4* pl = (uint4*)(g_xlo + (size_t)t * CC);
#pragma unroll
    for (int q = 0; q < 8; ++q) {
        ph[q] = make_uint4(hw[4*q], hw[4*q+1], hw[4*q+2], hw[4*q+3]);
        pl[q] = make_uint4(lw[4*q], lw[4*q+1], lw[4*q+2], lw[4*q+3]);
    }
}

// ---------------------------------------------------------------------------
// Kernel 2: projections y1 = W1 @ x, c = (W2 - W1) @ x
// ---------------------------------------------------------------------------
__global__ void k_proj(const float* __restrict__ x, const float* __restrict__ W) {
    __shared__ float Ws[OO * 2 * CC];
    int tid = threadIdx.x;
    for (int i = tid; i < OO * 2 * CC; i += blockDim.x) Ws[i] = W[i];
    __syncthreads();

    int t = blockIdx.x * blockDim.x + tid;
    int b = t >> 12;
    const float* xp = x + (size_t)b * CC * NN + (t & (NN - 1));
    float xc[CC];
#pragma unroll
    for (int c = 0; c < CC; ++c) xc[c] = xp[(size_t)c * NN];

    float* y1p = g_y1 + (size_t)t * OO;
    float* cp  = g_c  + (size_t)t * OO;
#pragma unroll 4
    for (int o = 0; o < OO; ++o) {
        const float* wr = Ws + o * 2 * CC;
        float a1 = 0.f, a2 = 0.f;
#pragma unroll
        for (int c = 0; c < CC; ++c) {
            a1 = fmaf(wr[c],      xc[c], a1);
            a2 = fmaf(wr[CC + c], xc[c], a2);
        }
        y1p[o] = a1;
        cp[o]  = a2 - a1;
    }
}

// ---------------------------------------------------------------------------
// Kernel 3: mma.sync kNN (round-4 structure + register prefetch of next B
// tile + float4 selection scan).  Grid 256, 256 threads, 1 CTA/SM.
// ---------------------------------------------------------------------------
#define SM_AHI 0
#define SM_ALO 16384
#define SM_BHI 32768
#define SM_BLO 40960
#define SM_XX  49152
#define SM_SCR 49408                       // 8 warps x 16 x 68 floats = 34816
#define SMEM_TOTAL 84224
#define SCR_STRIDE 68

__device__ __forceinline__ void tk_insert(float (&tv)[KK], int (&ti)[KK],
                                          float& vmin, int& minpos, float s, int j) {
#pragma unroll
    for (int k = 0; k < KK; ++k)
        if (k == minpos) { tv[k] = s; ti[k] = j; }
    float vm = tv[0]; int mp = 0;
#pragma unroll
    for (int k = 1; k < KK; ++k)
        if (tv[k] < vm) { vm = tv[k]; mp = k; }
    vmin = vm; minpos = mp;
}

__global__ void __launch_bounds__(256) k_knn_mma() {
    extern __shared__ char smem[];
    uint32_t sb = smem_u32(smem);
    int tid = threadIdx.x;
    int w   = tid >> 5;
    int l   = tid & 31;
    int b   = blockIdx.x >> 5;
    int ib  = blockIdx.x & 31;

    // ---- stage A tiles (128 rows x 64 bf16, hi+lo), sw128 swizzled ----
    {
        const uint4* Ah = (const uint4*)(g_xhi + ((size_t)b * NN + ib * 128) * CC);
        const uint4* Al = (const uint4*)(g_xlo + ((size_t)b * NN + ib * 128) * CC);
        for (int q = tid; q < 1024; q += 256) {
            uint32_t sw = sw128((uint32_t)q * 16);
            *(uint4*)(smem + SM_AHI + sw) = Ah[q];
            *(uint4*)(smem + SM_ALO + sw) = Al[q];
        }
    }

    float* scr = (float*)(smem + SM_SCR) + w * (16 * SCR_STRIDE);
    float* xxs = (float*)(smem + SM_XX);

    // ldmatrix lane roles
    uint32_t aRow = (uint32_t)(w * 16 + (l & 15));
    uint32_t aChunkBase = (uint32_t)(l >> 4);
    uint32_t bRowL  = (uint32_t)((l & 7) + ((l >> 4) & 1) * 8);
    uint32_t bChunk = (uint32_t)((l >> 3) & 1);

    int   srow    = l >> 1;
    int   colbase = (l & 1) * 32;
    const float* srowp = scr + srow * SCR_STRIDE;

    // ---- register prefetch of B tile (64 rows x 128B hi + lo) ----
    uint4 pfh[2], pfl[2];
    float xxpf = 0.f;
    auto ldg_tile = [&](int jt) {
        const uint4* Bh = (const uint4*)(g_xhi + ((size_t)b * NN + jt * 64) * CC);
        const uint4* Bl = (const uint4*)(g_xlo + ((size_t)b * NN + jt * 64) * CC);
        pfh[0] = Bh[tid]; pfh[1] = Bh[tid + 256];
        pfl[0] = Bl[tid]; pfl[1] = Bl[tid + 256];
        if (tid < 64) xxpf = g_xx[b * NN + jt * 64 + tid];
    };
    auto sts_tile = [&]() {
#pragma unroll
        for (int r = 0; r < 2; ++r) {
            uint32_t sw = sw128((uint32_t)(tid + r * 256) * 16);
            *(uint4*)(smem + SM_BHI + sw) = pfh[r];
            *(uint4*)(smem + SM_BLO + sw) = pfl[r];
        }
        if (tid < 64) xxs[tid] = xxpf;
    };

    ldg_tile(0);

    float tv[KK]; int ti[KK];
    float vmin = NEG_INF; int minpos = 0;

    for (int t = 0; t < 64; ++t) {
        int j0 = t * 64;
        sts_tile();
        __syncthreads();
        if (t < 63) ldg_tile(t + 1);      // latency hidden behind compute

        // ---- compute 16x64 scores per warp ----
        float acc[8][4];
#pragma unroll
        for (int nt = 0; nt < 8; ++nt)
#pragma unroll
            for (int q = 0; q < 4; ++q) acc[nt][q] = 0.f;

#pragma unroll
        for (int ks = 0; ks < 4; ++ks) {
            uint32_t aOff = sw128(aRow * 128 + (ks * 2 + aChunkBase) * 16);
            uint32_t ahi[4], alo[4];
            ldsm4(ahi, sb + SM_AHI + aOff);
            ldsm4(alo, sb + SM_ALO + aOff);
#pragma unroll
            for (int p = 0; p < 4; ++p) {
                uint32_t bOff = sw128((p * 16 + bRowL) * 128 + (ks * 2 + bChunk) * 16);
                uint32_t bh[4], bl[4];
                ldsm4(bh, sb + SM_BHI + bOff);
                ldsm4(bl, sb + SM_BLO + bOff);
                mma16816(acc[2*p],     ahi, bh[0], bh[1]);
                mma16816(acc[2*p + 1], ahi, bh[2], bh[3]);
                mma16816(acc[2*p],     ahi, bl[0], bl[1]);
                mma16816(acc[2*p + 1], ahi, bl[2], bl[3]);
                mma16816(acc[2*p],     alo, bh[0], bh[1]);
                mma16816(acc[2*p + 1], alo, bh[2], bh[3]);
            }
        }

        // ---- scores -> smem: s = 2*dot - xx[j] ----
        {
            int r0 = (l >> 2);
            int c0 = 2 * (l & 3);
#pragma unroll
            for (int nt = 0; nt < 8; ++nt) {
                float2 xv = *(const float2*)&xxs[nt * 8 + c0];
                float2 s01, s23;
                s01.x = fmaf(2.f, acc[nt][0], -xv.x);
                s01.y = fmaf(2.f, acc[nt][1], -xv.y);
                s23.x = fmaf(2.f, acc[nt][2], -xv.x);
                s23.y = fmaf(2.f, acc[nt][3], -xv.y);
                *(float2*)&scr[r0       * SCR_STRIDE + nt * 8 + c0] = s01;
                *(float2*)&scr[(r0 + 8) * SCR_STRIDE + nt * 8 + c0] = s23;
            }
        }
        __syncwarp();

        // ---- selection: each lane scans its half-row, float4 groups ----
        if (t == 0) {
#pragma unroll
            for (int q = 0; q < KK; ++q) {
                tv[q] = srowp[colbase + q];
                ti[q] = j0 + colbase + q;
            }
            float vm = tv[0]; int mp = 0;
#pragma unroll
            for (int k = 1; k < KK; ++k)
                if (tv[k] < vm) { vm = tv[k]; mp = k; }
            vmin = vm; minpos = mp;
#pragma unroll
            for (int q = KK; q < 32; ++q) {
                float sc = srowp[colbase + q];
                if (sc > vmin) tk_insert(tv, ti, vmin, minpos, sc, j0 + colbase + q);
            }
        } else {
#pragma unroll
            for (int g = 0; g < 8; ++g) {
                float4 v = *(const float4*)&srowp[colbase + g * 4];
                if (v.x > vmin || v.y > vmin || v.z > vmin || v.w > vmin) {
                    int jb = j0 + colbase + g * 4;
                    if (v.x > vmin) tk_insert(tv, ti, vmin, minpos, v.x, jb + 0);
                    if (v.y > vmin) tk_insert(tv, ti, vmin, minpos, v.y, jb + 1);
                    if (v.z > vmin) tk_insert(tv, ti, vmin, minpos, v.z, jb + 2);
                    if (v.w > vmin) tk_insert(tv, ti, vmin, minpos, v.w, jb + 3);
                }
            }
        }
        __syncthreads();
    }

    // ---- exact merge: 2 half-row top-20s -> row top-20 ----
    {
        float* mv = (float*)smem;                 // [128*2][20] vals
        int*   mi = (int*)(smem + 20480);         // [128*2][20] idx
        int rowg = w * 16 + srow;
        int half = l & 1;
#pragma unroll
        for (int k = 0; k < KK; ++k) {
            mv[(rowg * 2 + half) * KK + k] = tv[k];
            mi[(rowg * 2 + half) * KK + k] = ti[k];
        }
        __syncthreads();
        if (tid < 128) {
            float* v  = mv + tid * 2 * KK;
            int*   id = mi + tid * 2 * KK;
            int gi = b * NN + ib * 128 + tid;
            int* op = g_idx + (size_t)gi * KK;
            for (int s = 0; s < KK; ++s) {
                float best = NEG_INF; int bslot = 0;
#pragma unroll
                for (int q = 0; q < 2 * KK; ++q) {
                    float vv = v[q];
                    if (vv > best) { best = vv; bslot = q; }
                }
                op[s] = id[bslot];
                v[bslot] = NEG_INF;
            }
        }
    }
}

// ---------------------------------------------------------------------------
// Kernel 4: gather + max + leaky
// ---------------------------------------------------------------------------
__global__ void k_out(float* __restrict__ out) {
    int o  = threadIdx.x & 63;
    int nn = threadIdx.x >> 6;
    int t  = blockIdx.x * 4 + nn;
    int b  = t >> 12;
    int n  = t & (NN - 1);

    const int* ip = g_idx + (size_t)t * KK;
    float cadd = g_c[(size_t)t * OO + o];

    float m = NEG_INF;
#pragma unroll
    for (int k = 0; k < KK; ++k) {
        int j = ip[k];
        float v = g_y1[(((size_t)b * NN) + j) * OO + o];
        m = fmaxf(m, v);
    }
    float h = m + cadd;
    out[((size_t)b * OO + o) * NN + n] = (h >= 0.f) ? h : SLOPE * h;
}

// ---------------------------------------------------------------------------
extern "C" void kernel_launch(void* const* d_in, const int* in_sizes, int n_in,
                              void* d_out, int out_size) {
    const float* x = (const float*)d_in[0];
    const float* W = (const float*)d_in[1];
    float* out = (float*)d_out;

    static bool attr_set = false;
    if (!attr_set) {
        cudaFuncSetAttribute(k_knn_mma, cudaFuncAttributeMaxDynamicSharedMemorySize,
                             SMEM_TOTAL);
        attr_set = true;
    }

    k_pre    <<<BB * NN / 256, 256>>>(x);
    k_proj   <<<BB * NN / 128, 128>>>(x, W);
    k_knn_mma<<<256, 256, SMEM_TOTAL>>>();
    k_out    <<<BB * NN / 4, 256>>>(out);
}

// round 13
// speedup vs baseline: 9.8463x; 9.8463x over previous
#include <cuda_runtime.h>
#include <cuda_bf16.h>
#include <cstdint>

#define BB 8
#define CC 64
#define NN 4096
#define KK 20
#define OO 64
#define SLOPE 0.01f
#define NEG_INF __int_as_float(0xff800000)

// ---------------- scratch ----------------
__device__ float         g_xx [BB * NN];
__device__ __nv_bfloat16 g_xhi[BB * NN * CC];   // [b][n][c], 128B rows
__device__ __nv_bfloat16 g_xlo[BB * NN * CC];
__device__ float         g_y1 [BB * NN * OO];
__device__ float         g_c  [BB * NN * OO];
__device__ int           g_idx[BB * NN * KK];

// ---------------- helpers ----------------
__device__ __forceinline__ uint32_t smem_u32(const void* p) {
    uint32_t a;
    asm("{ .reg .u64 t; cvta.to.shared.u64 t, %1; cvt.u32.u64 %0, t; }"
        : "=r"(a) : "l"(p));
    return a;
}
__device__ __forceinline__ uint32_t sw128(uint32_t off) {
    return off ^ ((off >> 3) & 0x70);
}
__device__ __forceinline__ void ldsm4(uint32_t (&r)[4], uint32_t addr) {
    asm volatile("ldmatrix.sync.aligned.m8n8.x4.shared.b16 {%0,%1,%2,%3}, [%4];"
                 : "=r"(r[0]), "=r"(r[1]), "=r"(r[2]), "=r"(r[3]) : "r"(addr));
}
__device__ __forceinline__ void mma16816(float (&d)[4], const uint32_t (&a)[4],
                                         uint32_t b0, uint32_t b1) {
    asm volatile(
        "mma.sync.aligned.m16n8k16.row.col.f32.bf16.bf16.f32 "
        "{%0,%1,%2,%3}, {%4,%5,%6,%7}, {%8,%9}, {%0,%1,%2,%3};"
        : "+f"(d[0]), "+f"(d[1]), "+f"(d[2]), "+f"(d[3])
        : "r"(a[0]), "r"(a[1]), "r"(a[2]), "r"(a[3]), "r"(b0), "r"(b1));
}

// ---------------------------------------------------------------------------
// Kernel 1: fused xx + bf16 hi/lo split, transposed to [b][n][c]
// ---------------------------------------------------------------------------
__global__ void k_pre(const float* __restrict__ x) {
    int t = blockIdx.x * 256 + threadIdx.x;      // b*NN + n
    int b = t >> 12;
    const float* xp = x + (size_t)b * CC * NN + (t & (NN - 1));
    float s = 0.f;
    uint32_t hw[CC / 2], lw[CC / 2];
#pragma unroll
    for (int c2 = 0; c2 < CC / 2; ++c2) {
        float v0 = xp[(size_t)(2 * c2) * NN];
        float v1 = xp[(size_t)(2 * c2 + 1) * NN];
        s = fmaf(v0, v0, s);
        s = fmaf(v1, v1, s);
        __nv_bfloat16 h0 = __float2bfloat16(v0);
        __nv_bfloat16 h1 = __float2bfloat16(v1);
        __nv_bfloat16 l0 = __float2bfloat16(v0 - __bfloat162float(h0));
        __nv_bfloat16 l1 = __float2bfloat16(v1 - __bfloat162float(h1));
        hw[c2] = (uint32_t)__bfloat16_as_ushort(h0) |
                 ((uint32_t)__bfloat16_as_ushort(h1) << 16);
        lw[c2] = (uint32_t)__bfloat16_as_ushort(l0) |
                 ((uint32_t)__bfloat16_as_ushort(l1) << 16);
    }
    g_xx[t] = s;
    uint4* ph = (uint4*)(g_xhi + (size_t)t * CC);
    uint4* pl = (uint4*)(g_xlo + (size_t)t * CC);
#pragma unroll
    for (int q = 0; q < 8; ++q) {
        ph[q] = make_uint4(hw[4*q], hw[4*q+1], hw[4*q+2], hw[4*q+3]);
        pl[q] = make_uint4(lw[4*q], lw[4*q+1], lw[4*q+2], lw[4*q+3]);
    }
}

// ---------------------------------------------------------------------------
// Kernel 2: projections y1 = W1 @ x, c = (W2 - W1) @ x
// ---------------------------------------------------------------------------
__global__ void k_proj(const float* __restrict__ x, const float* __restrict__ W) {
    __shared__ float Ws[OO * 2 * CC];
    int tid = threadIdx.x;
    for (int i = tid; i < OO * 2 * CC; i += blockDim.x) Ws[i] = W[i];
    __syncthreads();

    int t = blockIdx.x * blockDim.x + tid;
    int b = t >> 12;
    const float* xp = x + (size_t)b * CC * NN + (t & (NN - 1));
    float xc[CC];
#pragma unroll
    for (int c = 0; c < CC; ++c) xc[c] = xp[(size_t)c * NN];

    float* y1p = g_y1 + (size_t)t * OO;
    float* cp  = g_c  + (size_t)t * OO;
#pragma unroll 4
    for (int o = 0; o < OO; ++o) {
        const float* wr = Ws + o * 2 * CC;
        float a1 = 0.f, a2 = 0.f;
#pragma unroll
        for (int c = 0; c < CC; ++c) {
            a1 = fmaf(wr[c],      xc[c], a1);
            a2 = fmaf(wr[CC + c], xc[c], a2);
        }
        y1p[o] = a1;
        cp[o]  = a2 - a1;
    }
}

// ---------------------------------------------------------------------------
// Kernel 3: mma.sync kNN.  Round-4 mainloop + register prefetch of next B
// tile; top-K lists moved to SMEM (frees ~40 regs -> no spill headroom issue).
// Grid 256 = 8 batches x 32 i-blocks, 256 threads.
// ---------------------------------------------------------------------------
#define SM_AHI 0
#define SM_ALO 16384
#define SM_BHI 32768
#define SM_BLO 40960
#define SM_XX  49152
#define SM_SCR 49408                       // 8 warps x 16 x 68 floats = 34816
#define SM_TKV 84224                       // KK x 256 floats = 20480
#define SM_TKI 104704                      // KK x 256 ints   = 20480
#define SMEM_TOTAL 125184
#define SCR_STRIDE 68

__global__ void __launch_bounds__(256) k_knn_mma() {
    extern __shared__ char smem[];
    uint32_t sb = smem_u32(smem);
    int tid = threadIdx.x;
    int w   = tid >> 5;
    int l   = tid & 31;
    int b   = blockIdx.x >> 5;
    int ib  = blockIdx.x & 31;

    // ---- stage A tiles (128 rows x 64 bf16, hi+lo), sw128 swizzled ----
    {
        const uint4* Ah = (const uint4*)(g_xhi + ((size_t)b * NN + ib * 128) * CC);
        const uint4* Al = (const uint4*)(g_xlo + ((size_t)b * NN + ib * 128) * CC);
        for (int q = tid; q < 1024; q += 256) {
            uint32_t sw = sw128((uint32_t)q * 16);
            *(uint4*)(smem + SM_AHI + sw) = Ah[q];
            *(uint4*)(smem + SM_ALO + sw) = Al[q];
        }
    }

    float* scr = (float*)(smem + SM_SCR) + w * (16 * SCR_STRIDE);
    float* xxs = (float*)(smem + SM_XX);
    float* tkv = (float*)(smem + SM_TKV);   // [KK][256] per-thread columns
    int*   tki = (int*)  (smem + SM_TKI);

    // ldmatrix lane roles
    uint32_t aRow = (uint32_t)(w * 16 + (l & 15));
    uint32_t aChunkBase = (uint32_t)(l >> 4);
    uint32_t bRowL  = (uint32_t)((l & 7) + ((l >> 4) & 1) * 8);
    uint32_t bChunk = (uint32_t)((l >> 3) & 1);

    int   srow    = l >> 1;
    int   colbase = (l & 1) * 32;
    const float* srowp = scr + srow * SCR_STRIDE;

    float vmin = NEG_INF;
    int   minpos = 0;

    // smem-resident top-K insert (rescans 20 conflict-free LDS)
    auto tk_ins = [&](float s, int j) {
        tkv[minpos * 256 + tid] = s;
        tki[minpos * 256 + tid] = j;
        float vm = tkv[tid]; int mp = 0;
#pragma unroll
        for (int k = 1; k < KK; ++k) {
            float v = tkv[k * 256 + tid];
            if (v < vm) { vm = v; mp = k; }
        }
        vmin = vm; minpos = mp;
    };

    // ---- register prefetch of B tile (64 rows x 128B hi + lo) ----
    uint4 pfh0, pfh1, pfl0, pfl1;
    float xxpf = 0.f;
    {
        const uint4* Bh = (const uint4*)(g_xhi + (size_t)b * NN * CC);
        const uint4* Bl = (const uint4*)(g_xlo + (size_t)b * NN * CC);
        pfh0 = Bh[tid]; pfh1 = Bh[tid + 256];
        pfl0 = Bl[tid]; pfl1 = Bl[tid + 256];
        if (tid < 64) xxpf = g_xx[b * NN + tid];
    }

    uint32_t sw0 = sw128((uint32_t)tid * 16);
    uint32_t sw1 = sw128((uint32_t)(tid + 256) * 16);

    for (int t = 0; t < 64; ++t) {
        int j0 = t * 64;
        // ---- store prefetched tile to smem ----
        *(uint4*)(smem + SM_BHI + sw0) = pfh0;
        *(uint4*)(smem + SM_BHI + sw1) = pfh1;
        *(uint4*)(smem + SM_BLO + sw0) = pfl0;
        *(uint4*)(smem + SM_BLO + sw1) = pfl1;
        if (tid < 64) xxs[tid] = xxpf;
        __syncthreads();

        // ---- prefetch next tile (latency hidden behind compute) ----
        if (t < 63) {
            const uint4* Bh = (const uint4*)(g_xhi + ((size_t)b * NN + (t + 1) * 64) * CC);
            const uint4* Bl = (const uint4*)(g_xlo + ((size_t)b * NN + (t + 1) * 64) * CC);
            pfh0 = Bh[tid]; pfh1 = Bh[tid + 256];
            pfl0 = Bl[tid]; pfl1 = Bl[tid + 256];
            if (tid < 64) xxpf = g_xx[b * NN + (t + 1) * 64 + tid];
        }

        // ---- compute 16x64 scores per warp ----
        float acc[8][4];
#pragma unroll
        for (int nt = 0; nt < 8; ++nt)
#pragma unroll
            for (int q = 0; q < 4; ++q) acc[nt][q] = 0.f;

#pragma unroll
        for (int ks = 0; ks < 4; ++ks) {
            uint32_t aOff = sw128(aRow * 128 + (ks * 2 + aChunkBase) * 16);
            uint32_t ahi[4], alo[4];
            ldsm4(ahi, sb + SM_AHI + aOff);
            ldsm4(alo, sb + SM_ALO + aOff);
#pragma unroll
            for (int p = 0; p < 4; ++p) {
                uint32_t bOff = sw128((p * 16 + bRowL) * 128 + (ks * 2 + bChunk) * 16);
                uint32_t bh[4], bl[4];
                ldsm4(bh, sb + SM_BHI + bOff);
                ldsm4(bl, sb + SM_BLO + bOff);
                mma16816(acc[2*p],     ahi, bh[0], bh[1]);
                mma16816(acc[2*p + 1], ahi, bh[2], bh[3]);
                mma16816(acc[2*p],     ahi, bl[0], bl[1]);
                mma16816(acc[2*p + 1], ahi, bl[2], bl[3]);
                mma16816(acc[2*p],     alo, bh[0], bh[1]);
                mma16816(acc[2*p + 1], alo, bh[2], bh[3]);
            }
        }

        // ---- scores -> smem: s = 2*dot - xx[j] ----
        {
            int r0 = (l >> 2);
            int c0 = 2 * (l & 3);
#pragma unroll
            for (int nt = 0; nt < 8; ++nt) {
                float2 xv = *(const float2*)&xxs[nt * 8 + c0];
                float2 s01, s23;
                s01.x = fmaf(2.f, acc[nt][0], -xv.x);
                s01.y = fmaf(2.f, acc[nt][1], -xv.y);
                s23.x = fmaf(2.f, acc[nt][2], -xv.x);
                s23.y = fmaf(2.f, acc[nt][3], -xv.y);
                *(float2*)&scr[r0       * SCR_STRIDE + nt * 8 + c0] = s01;
                *(float2*)&scr[(r0 + 8) * SCR_STRIDE + nt * 8 + c0] = s23;
            }
        }
        __syncwarp();

        // ---- selection: each lane scans its half-row, float4 groups ----
        if (t == 0) {
#pragma unroll
            for (int q = 0; q < KK; ++q) {
                tkv[q * 256 + tid] = srowp[colbase + q];
                tki[q * 256 + tid] = j0 + colbase + q;
            }
            float vm = tkv[tid]; int mp = 0;
#pragma unroll
            for (int k = 1; k < KK; ++k) {
                float v = tkv[k * 256 + tid];
                if (v < vm) { vm = v; mp = k; }
            }
            vmin = vm; minpos = mp;
#pragma unroll
            for (int q = KK; q < 32; ++q) {
                float sc = srowp[colbase + q];
                if (sc > vmin) tk_ins(sc, j0 + colbase + q);
            }
        } else {
#pragma unroll
            for (int g = 0; g < 8; ++g) {
                float4 v = *(const float4*)&srowp[colbase + g * 4];
                if (v.x > vmin || v.y > vmin || v.z > vmin || v.w > vmin) {
                    int jb = j0 + colbase + g * 4;
                    if (v.x > vmin) tk_ins(v.x, jb + 0);
                    if (v.y > vmin) tk_ins(v.y, jb + 1);
                    if (v.z > vmin) tk_ins(v.z, jb + 2);
                    if (v.w > vmin) tk_ins(v.w, jb + 3);
                }
            }
        }
        __syncthreads();
    }

    // ---- exact merge: 2 half-row top-20s -> row top-20 (lists in smem) ----
    if (tid < 128) {
        int t0 = (tid >> 4) * 32 + (tid & 15) * 2;   // owner threads t0, t0+1
        int gi = b * NN + ib * 128 + tid;            // rowg == tid
        int* op = g_idx + (size_t)gi * KK;
        for (int s = 0; s < KK; ++s) {
            float best = NEG_INF; int bk = 0, bt = t0;
#pragma unroll
            for (int k = 0; k < KK; ++k) {
                float v0 = tkv[k * 256 + t0];
                float v1 = tkv[k * 256 + t0 + 1];
                if (v0 > best) { best = v0; bk = k; bt = t0; }
                if (v1 > best) { best = v1; bk = k; bt = t0 + 1; }
            }
            op[s] = tki[bk * 256 + bt];
            tkv[bk * 256 + bt] = NEG_INF;
        }
    }
}

// ---------------------------------------------------------------------------
// Kernel 4: gather + max + leaky
// ---------------------------------------------------------------------------
__global__ void k_out(float* __restrict__ out) {
    int o  = threadIdx.x & 63;
    int nn = threadIdx.x >> 6;
    int t  = blockIdx.x * 4 + nn;
    int b  = t >> 12;
    int n  = t & (NN - 1);

    const int* ip = g_idx + (size_t)t * KK;
    float cadd = g_c[(size_t)t * OO + o];

    float m = NEG_INF;
#pragma unroll
    for (int k = 0; k < KK; ++k) {
        int j = ip[k];
        float v = g_y1[(((size_t)b * NN) + j) * OO + o];
        m = fmaxf(m, v);
    }
    float h = m + cadd;
    out[((size_t)b * OO + o) * NN + n] = (h >= 0.f) ? h : SLOPE * h;
}

// ---------------------------------------------------------------------------
extern "C" void kernel_launch(void* const* d_in, const int* in_sizes, int n_in,
                              void* d_out, int out_size) {
    const float* x = (const float*)d_in[0];
    const float* W = (const float*)d_in[1];
    float* out = (float*)d_out;

    static bool attr_set = false;
    if (!attr_set) {
        cudaFuncSetAttribute(k_knn_mma, cudaFuncAttributeMaxDynamicSharedMemorySize,
                             SMEM_TOTAL);
        attr_set = true;
    }

    k_pre    <<<BB * NN / 256, 256>>>(x);
    k_proj   <<<BB * NN / 128, 128>>>(x, W);
    k_knn_mma<<<256, 256, SMEM_TOTAL>>>();
    k_out    <<<BB * NN / 4, 256>>>(out);
}

// round 14
// speedup vs baseline: 13.4223x; 1.3632x over previous
#include <cuda_runtime.h>
#include <cuda_bf16.h>
#include <cstdint>

#define BB 8
#define CC 64
#define NN 4096
#define KK 20
#define OO 64
#define SLOPE 0.01f
#define NEG_INF __int_as_float(0xff800000)

// ---------------- scratch ----------------
__device__ float         g_xx [BB * NN];
__device__ __nv_bfloat16 g_xhi[BB * NN * CC];   // [b][n][c], 128B rows
__device__ __nv_bfloat16 g_xlo[BB * NN * CC];
__device__ float         g_y1 [BB * NN * OO];
__device__ float         g_c  [BB * NN * OO];
__device__ int           g_idx[BB * NN * KK];

// ---------------- helpers ----------------
__device__ __forceinline__ uint32_t smem_u32(const void* p) {
    uint32_t a;
    asm("{ .reg .u64 t; cvta.to.shared.u64 t, %1; cvt.u32.u64 %0, t; }"
        : "=r"(a) : "l"(p));
    return a;
}
__device__ __forceinline__ uint32_t sw128(uint32_t off) {
    return off ^ ((off >> 3) & 0x70);
}
__device__ __forceinline__ void ldsm4(uint32_t (&r)[4], uint32_t addr) {
    asm volatile("ldmatrix.sync.aligned.m8n8.x4.shared.b16 {%0,%1,%2,%3}, [%4];"
                 : "=r"(r[0]), "=r"(r[1]), "=r"(r[2]), "=r"(r[3]) : "r"(addr));
}
__device__ __forceinline__ void mma16816(float (&d)[4], const uint32_t (&a)[4],
                                         uint32_t b0, uint32_t b1) {
    asm volatile(
        "mma.sync.aligned.m16n8k16.row.col.f32.bf16.bf16.f32 "
        "{%0,%1,%2,%3}, {%4,%5,%6,%7}, {%8,%9}, {%0,%1,%2,%3};"
        : "+f"(d[0]), "+f"(d[1]), "+f"(d[2]), "+f"(d[3])
        : "r"(a[0]), "r"(a[1]), "r"(a[2]), "r"(a[3]), "r"(b0), "r"(b1));
}

// ---------------------------------------------------------------------------
// Kernel 1: fused xx + bf16 hi/lo split, transposed to [b][n][c]
// ---------------------------------------------------------------------------
__global__ void k_pre(const float* __restrict__ x) {
    int t = blockIdx.x * 256 + threadIdx.x;      // b*NN + n
    int b = t >> 12;
    const float* xp = x + (size_t)b * CC * NN + (t & (NN - 1));
    float s = 0.f;
    uint32_t hw[CC / 2], lw[CC / 2];
#pragma unroll
    for (int c2 = 0; c2 < CC / 2; ++c2) {
        float v0 = xp[(size_t)(2 * c2) * NN];
        float v1 = xp[(size_t)(2 * c2 + 1) * NN];
        s = fmaf(v0, v0, s);
        s = fmaf(v1, v1, s);
        __nv_bfloat16 h0 = __float2bfloat16(v0);
        __nv_bfloat16 h1 = __float2bfloat16(v1);
        __nv_bfloat16 l0 = __float2bfloat16(v0 - __bfloat162float(h0));
        __nv_bfloat16 l1 = __float2bfloat16(v1 - __bfloat162float(h1));
        hw[c2] = (uint32_t)__bfloat16_as_ushort(h0) |
                 ((uint32_t)__bfloat16_as_ushort(h1) << 16);
        lw[c2] = (uint32_t)__bfloat16_as_ushort(l0) |
                 ((uint32_t)__bfloat16_as_ushort(l1) << 16);
    }
    g_xx[t] = s;
    uint4* ph = (uint4*)(g_xhi + (size_t)t * CC);
    uint4* pl = (uint4*)(g_xlo + (size_t)t * CC);
#pragma unroll
    for (int q = 0; q < 8; ++q) {
        ph[q] = make_uint4(hw[4*q], hw[4*q+1], hw[4*q+2], hw[4*q+3]);
        pl[q] = make_uint4(lw[4*q], lw[4*q+1], lw[4*q+2], lw[4*q+3]);
    }
}

// ---------------------------------------------------------------------------
// Kernel 2: projections y1 = W1 @ x, c = (W2 - W1) @ x
// ---------------------------------------------------------------------------
__global__ void k_proj(const float* __restrict__ x, const float* __restrict__ W) {
    __shared__ float Ws[OO * 2 * CC];
    int tid = threadIdx.x;
    for (int i = tid; i < OO * 2 * CC; i += blockDim.x) Ws[i] = W[i];
    __syncthreads();

    int t = blockIdx.x * blockDim.x + tid;
    int b = t >> 12;
    const float* xp = x + (size_t)b * CC * NN + (t & (NN - 1));
    float xc[CC];
#pragma unroll
    for (int c = 0; c < CC; ++c) xc[c] = xp[(size_t)c * NN];

    float* y1p = g_y1 + (size_t)t * OO;
    float* cp  = g_c  + (size_t)t * OO;
#pragma unroll 4
    for (int o = 0; o < OO; ++o) {
        const float* wr = Ws + o * 2 * CC;
        float a1 = 0.f, a2 = 0.f;
#pragma unroll
        for (int c = 0; c < CC; ++c) {
            a1 = fmaf(wr[c],      xc[c], a1);
            a2 = fmaf(wr[CC + c], xc[c], a2);
        }
        y1p[o] = a1;
        cp[o]  = a2 - a1;
    }
}

// ---------------------------------------------------------------------------
// Kernel 3: mma.sync kNN with threshold-filtered selection.
// Champion (R4) mainloop: LDG->STS B tiles, 96 mma/tile/warp.
// Epilogue: scores stay in registers, compared against per-row threshold;
// passers appended to per-row candidate buffers (smem atomics, cap 64 =
// guaranteed bound); 128 owner threads drain into per-row top-20 lists.
// Grid 256 = 8 batches x 32 i-blocks, 256 threads.
// ---------------------------------------------------------------------------
#define SM_AHI  0
#define SM_ALO  16384
#define SM_BHI  32768
#define SM_BLO  40960
#define SM_XX   49152                      // 64 floats
#define SM_RMIN 49408                      // 128 floats: per-row threshold
#define SM_CNT  49920                      // 128 ints:   per-row candidate count
#define SM_TKV  50432                      // [KK][128] floats = 10240
#define SM_TKI  60672                      // [KK][128] ints   = 10240
#define SM_CV   70912                      // [64][128] floats = 32768
#define SM_CI   103680                     // [64][128] ints   = 32768
#define SMEM_TOTAL 136448

__global__ void __launch_bounds__(256) k_knn_mma() {
    extern __shared__ char smem[];
    uint32_t sb = smem_u32(smem);
    int tid = threadIdx.x;
    int w   = tid >> 5;
    int l   = tid & 31;
    int b   = blockIdx.x >> 5;
    int ib  = blockIdx.x & 31;

    float* xxs    = (float*)(smem + SM_XX);
    float* rowmin = (float*)(smem + SM_RMIN);
    int*   cnt    = (int*)  (smem + SM_CNT);
    float* tkv    = (float*)(smem + SM_TKV);
    int*   tki    = (int*)  (smem + SM_TKI);
    float* cv     = (float*)(smem + SM_CV);
    int*   ci     = (int*)  (smem + SM_CI);

    // ---- init per-row state ----
    if (tid < 128) {
        rowmin[tid] = NEG_INF;
        cnt[tid] = 64;                     // tile 0 fills all 64 slots
#pragma unroll
        for (int k = 0; k < KK; ++k) tkv[k * 128 + tid] = NEG_INF;
    }

    // ---- stage A tiles (128 rows x 64 bf16, hi+lo), sw128 swizzled ----
    {
        const uint4* Ah = (const uint4*)(g_xhi + ((size_t)b * NN + ib * 128) * CC);
        const uint4* Al = (const uint4*)(g_xlo + ((size_t)b * NN + ib * 128) * CC);
        for (int q = tid; q < 1024; q += 256) {
            uint32_t sw = sw128((uint32_t)q * 16);
            *(uint4*)(smem + SM_AHI + sw) = Ah[q];
            *(uint4*)(smem + SM_ALO + sw) = Al[q];
        }
    }

    // ldmatrix lane roles
    uint32_t aRow = (uint32_t)(w * 16 + (l & 15));
    uint32_t aChunkBase = (uint32_t)(l >> 4);
    uint32_t bRowL  = (uint32_t)((l & 7) + ((l >> 4) & 1) * 8);
    uint32_t bChunk = (uint32_t)((l >> 3) & 1);

    // epilogue fragment roles (m16n8k16 layout)
    int gr0 = w * 16 + (l >> 2);           // CTA-local row of acc[nt][0..1]
    int gr1 = gr0 + 8;                     // CTA-local row of acc[nt][2..3]
    int c0  = 2 * (l & 3);                 // col offset within 8-col block

    // owner-thread selection state (tid < 128 owns row tid)
    float vmin = NEG_INF;
    int   minpos = 0;

    for (int t = 0; t < 64; ++t) {
        int j0 = t * 64;
        // ---- stage B tile (64 rows x 64 bf16, hi+lo) + xx slice ----
        {
            const uint4* Bh = (const uint4*)(g_xhi + ((size_t)b * NN + j0) * CC);
            const uint4* Bl = (const uint4*)(g_xlo + ((size_t)b * NN + j0) * CC);
            for (int q = tid; q < 512; q += 256) {
                uint32_t sw = sw128((uint32_t)q * 16);
                *(uint4*)(smem + SM_BHI + sw) = Bh[q];
                *(uint4*)(smem + SM_BLO + sw) = Bl[q];
            }
            if (tid < 64) xxs[tid] = g_xx[b * NN + j0 + tid];
        }
        __syncthreads();

        // ---- compute 16x64 scores per warp (3 bf16 products, fp32 acc) ----
        float acc[8][4];
#pragma unroll
        for (int nt = 0; nt < 8; ++nt)
#pragma unroll
            for (int q = 0; q < 4; ++q) acc[nt][q] = 0.f;

#pragma unroll
        for (int ks = 0; ks < 4; ++ks) {
            uint32_t aOff = sw128(aRow * 128 + (ks * 2 + aChunkBase) * 16);
            uint32_t ahi[4], alo[4];
            ldsm4(ahi, sb + SM_AHI + aOff);
            ldsm4(alo, sb + SM_ALO + aOff);
#pragma unroll
            for (int p = 0; p < 4; ++p) {
                uint32_t bOff = sw128((p * 16 + bRowL) * 128 + (ks * 2 + bChunk) * 16);
                uint32_t bh[4], bl[4];
                ldsm4(bh, sb + SM_BHI + bOff);
                ldsm4(bl, sb + SM_BLO + bOff);
                mma16816(acc[2*p],     ahi, bh[0], bh[1]);
                mma16816(acc[2*p + 1], ahi, bh[2], bh[3]);
                mma16816(acc[2*p],     ahi, bl[0], bl[1]);
                mma16816(acc[2*p + 1], ahi, bl[2], bl[3]);
                mma16816(acc[2*p],     alo, bh[0], bh[1]);
                mma16816(acc[2*p + 1], alo, bh[2], bh[3]);
            }
        }

        // ---- epilogue: scores in regs -> threshold filter -> candidates ----
        if (t == 0) {
            // all 64 cols are candidates; deterministic slot = column index
#pragma unroll
            for (int nt = 0; nt < 8; ++nt) {
                int jc = nt * 8 + c0;
                float2 xv = *(const float2*)&xxs[jc];
                float s0 = fmaf(2.f, acc[nt][0], -xv.x);
                float s1 = fmaf(2.f, acc[nt][1], -xv.y);
                float s2 = fmaf(2.f, acc[nt][2], -xv.x);
                float s3 = fmaf(2.f, acc[nt][3], -xv.y);
                cv[jc * 128 + gr0] = s0;  ci[jc * 128 + gr0] = jc;
                cv[(jc+1) * 128 + gr0] = s1;  ci[(jc+1) * 128 + gr0] = jc + 1;
                cv[jc * 128 + gr1] = s2;  ci[jc * 128 + gr1] = jc;
                cv[(jc+1) * 128 + gr1] = s3;  ci[(jc+1) * 128 + gr1] = jc + 1;
            }
        } else {
            float th0 = rowmin[gr0];
            float th1 = rowmin[gr1];
#pragma unroll
            for (int nt = 0; nt < 8; ++nt) {
                int jc = nt * 8 + c0;
                float2 xv = *(const float2*)&xxs[jc];
                float s0 = fmaf(2.f, acc[nt][0], -xv.x);
                float s1 = fmaf(2.f, acc[nt][1], -xv.y);
                float s2 = fmaf(2.f, acc[nt][2], -xv.x);
                float s3 = fmaf(2.f, acc[nt][3], -xv.y);
                bool p0 = s0 > th0, p1 = s1 > th0, p2 = s2 > th1, p3 = s3 > th1;
                if (p0 | p1 | p2 | p3) {
                    if (p0) { int sl = atomicAdd(&cnt[gr0], 1);
                              cv[sl * 128 + gr0] = s0; ci[sl * 128 + gr0] = j0 + jc; }
                    if (p1) { int sl = atomicAdd(&cnt[gr0], 1);
                              cv[sl * 128 + gr0] = s1; ci[sl * 128 + gr0] = j0 + jc + 1; }
                    if (p2) { int sl = atomicAdd(&cnt[gr1], 1);
                              cv[sl * 128 + gr1] = s2; ci[sl * 128 + gr1] = j0 + jc; }
                    if (p3) { int sl = atomicAdd(&cnt[gr1], 1);
                              cv[sl * 128 + gr1] = s3; ci[sl * 128 + gr1] = j0 + jc + 1; }
                }
            }
        }
        __syncthreads();

        // ---- drain: owner thread per row, exact insert, refresh threshold ----
        if (tid < 128) {
            int n = cnt[tid];
            for (int u = 0; u < n; ++u) {
                float s = cv[u * 128 + tid];
                if (s > vmin) {
                    tkv[minpos * 128 + tid] = s;
                    tki[minpos * 128 + tid] = ci[u * 128 + tid];
                    float vm = tkv[tid]; int mp = 0;
#pragma unroll
                    for (int k = 1; k < KK; ++k) {
                        float v = tkv[k * 128 + tid];
                        if (v < vm) { vm = v; mp = k; }
                    }
                    vmin = vm; minpos = mp;
                }
            }
            rowmin[tid] = vmin;
            cnt[tid] = 0;
        }
        // next iteration's __syncthreads (after B STS) orders drain vs epilogue
    }

    __syncthreads();
    // ---- writeback (order irrelevant: downstream is max-pool) ----
    if (tid < 128) {
        int* op = g_idx + (size_t)(b * NN + ib * 128 + tid) * KK;
#pragma unroll
        for (int k = 0; k < KK; ++k) op[k] = tki[k * 128 + tid];
    }
}

// ---------------------------------------------------------------------------
// Kernel 4: gather + max + leaky
// ---------------------------------------------------------------------------
__global__ void k_out(float* __restrict__ out) {
    int o  = threadIdx.x & 63;
    int nn = threadIdx.x >> 6;
    int t  = blockIdx.x * 4 + nn;
    int b  = t >> 12;
    int n  = t & (NN - 1);

    const int* ip = g_idx + (size_t)t * KK;
    float cadd = g_c[(size_t)t * OO + o];

    float m = NEG_INF;
#pragma unroll
    for (int k = 0; k < KK; ++k) {
        int j = ip[k];
        float v = g_y1[(((size_t)b * NN) + j) * OO + o];
        m = fmaxf(m, v);
    }
    float h = m + cadd;
    out[((size_t)b * OO + o) * NN + n] = (h >= 0.f) ? h : SLOPE * h;
}

// ---------------------------------------------------------------------------
extern "C" void kernel_launch(void* const* d_in, const int* in_sizes, int n_in,
                              void* d_out, int out_size) {
    const float* x = (const float*)d_in[0];
    const float* W = (const float*)d_in[1];
    float* out = (float*)d_out;

    static bool attr_set = false;
    if (!attr_set) {
        cudaFuncSetAttribute(k_knn_mma, cudaFuncAttributeMaxDynamicSharedMemorySize,
                             SMEM_TOTAL);
        attr_set = true;
    }

    k_pre    <<<BB * NN / 256, 256>>>(x);
    k_proj   <<<BB * NN / 128, 128>>>(x, W);
    k_knn_mma<<<256, 256, SMEM_TOTAL>>>();
    k_out    <<<BB * NN / 4, 256>>>(out);
}